// round 2
// baseline (speedup 1.0000x reference)
#include <cuda_runtime.h>
#include <math.h>

#define Bq 16
#define CIN 32
#define CCOND 100
#define LC 512
#define HOP 8
#define HID 64
#define NL 4
#define COUT 64
#define TT 4096
#define KD 192          // 64*3 features for the k=3 conv-as-GEMM
#define NLAY 6144       // CIN*COUT*3 = per-layer kernel channels
#define SLOPE 0.2f

// ---------------- scratch (static __device__, no allocations) ----------------
__device__ float d_h[Bq * HID * LC];
__device__ float d_tmp[Bq * HID * LC];
__device__ float d_A[Bq * LC * KD];                    // im2col of h: 8192 x 192
__device__ float d_kern[(size_t)Bq * LC * NLAY];       // per-layer slice [m][ci][o][k] (~201MB)
__device__ float d_kbias[Bq * LC * NL * COUT];         // [m][layer][o]
__device__ float d_xx0[Bq * CIN * TT];
__device__ float d_xx1[Bq * CIN * TT];

__device__ __forceinline__ float lrelu(float v) { return v >= 0.f ? v : SLOPE * v; }

// ---------------- kernel predictor: input conv (k=5, pad=2) + lrelu ----------------
__global__ void conv_in_k(const float* __restrict__ c, const float* __restrict__ w,
                          const float* __restrict__ b) {
    int co = blockIdx.x, bb = blockIdx.y, l = threadIdx.x;
    const float* cb = c + (size_t)bb * CCOND * LC;
    const float* wr = w + co * CCOND * 5;
    float acc = b[co];
    for (int ci = 0; ci < CCOND; ci++) {
        const float* cr = cb + ci * LC;
#pragma unroll
        for (int kk = 0; kk < 5; kk++) {
            int t = l + kk - 2;
            float xv = (t >= 0 && t < LC) ? cr[t] : 0.f;
            acc += xv * wr[ci * 5 + kk];
        }
    }
    d_h[((size_t)bb * HID + co) * LC + l] = lrelu(acc);
}

// ---------------- residual-block conv (k=3, pad=1), lrelu, optional add ----------------
__global__ void conv_res_k(const float* __restrict__ w, const float* __restrict__ b,
                           int srcTmp, int dstTmp, int doAdd) {
    int co = blockIdx.x, bb = blockIdx.y, l = threadIdx.x;
    const float* in = srcTmp ? d_tmp : d_h;
    float* out = dstTmp ? d_tmp : d_h;
    const float* ib = in + (size_t)bb * HID * LC;
    const float* wr = w + co * HID * 3;
    float acc = b[co];
    for (int ci = 0; ci < HID; ci++) {
        const float* xr = ib + ci * LC;
        float x0 = (l > 0) ? xr[l - 1] : 0.f;
        float x1 = xr[l];
        float x2 = (l < LC - 1) ? xr[l + 1] : 0.f;
        acc += x0 * wr[ci * 3] + x1 * wr[ci * 3 + 1] + x2 * wr[ci * 3 + 2];
    }
    acc = lrelu(acc);
    if (doAdd) acc += d_h[((size_t)bb * HID + co) * LC + l];
    out[((size_t)bb * HID + co) * LC + l] = acc;
}

// ---------------- im2col: A[m][c2*3+kk] = h[b][c2][l+kk-1] ----------------
__global__ void build_A_k() {
    int m = blockIdx.x;
    int bb = m / LC, l = m % LC;
    int f = threadIdx.x;            // 192
    int c2 = f / 3, kk = f % 3;
    int t = l + kk - 1;
    d_A[(size_t)m * KD + f] = (t >= 0 && t < LC) ? d_h[((size_t)bb * HID + c2) * LC + t] : 0.f;
}

// ---------------- main GEMM (per layer): C[m][n] = sum_f A[m][f]*W[n][f] + kb[n] ----------------
// M=8192, N=6144, K=192. 128x128 tiles, 8x8 per thread, double-buffered smem.
#define BM 128
#define BN 128
#define BK 16
__global__ void __launch_bounds__(256) gemm_k(const float* __restrict__ W,
                                              const float* __restrict__ kb) {
    __shared__ float As[2][BK][BM + 4];
    __shared__ float Bs[2][BK][BN + 4];
    int bn = blockIdx.x, bm = blockIdx.y, tid = threadIdx.x;
    const float* Ap = d_A + (size_t)bm * BM * KD;
    const float* Bp = W + (size_t)bn * BN * KD;
    float acc[8][8];
#pragma unroll
    for (int i = 0; i < 8; i++)
#pragma unroll
        for (int j = 0; j < 8; j++) acc[i][j] = 0.f;
    int mfrag = (tid >> 4) << 3;
    int nfrag = (tid & 15) << 3;

    auto load = [&](int buf, int k0) {
#pragma unroll
        for (int i = 0; i < 2; i++) {
            int v = tid + i * 256;
            int row = v >> 2, cg = (v & 3) << 2;
            float4 a = *(const float4*)(Ap + (size_t)row * KD + k0 + cg);
            As[buf][cg + 0][row] = a.x; As[buf][cg + 1][row] = a.y;
            As[buf][cg + 2][row] = a.z; As[buf][cg + 3][row] = a.w;
            float4 bq = *(const float4*)(Bp + (size_t)row * KD + k0 + cg);
            Bs[buf][cg + 0][row] = bq.x; Bs[buf][cg + 1][row] = bq.y;
            Bs[buf][cg + 2][row] = bq.z; Bs[buf][cg + 3][row] = bq.w;
        }
    };
    load(0, 0);
    __syncthreads();
    const int NT = KD / BK;  // 12
    for (int kt = 0; kt < NT; kt++) {
        int cur = kt & 1;
        if (kt + 1 < NT) load(cur ^ 1, (kt + 1) * BK);
#pragma unroll
        for (int k = 0; k < BK; k++) {
            float af[8], bf[8];
#pragma unroll
            for (int i = 0; i < 8; i += 4) *(float4*)&af[i] = *(const float4*)&As[cur][k][mfrag + i];
#pragma unroll
            for (int j = 0; j < 8; j += 4) *(float4*)&bf[j] = *(const float4*)&Bs[cur][k][nfrag + j];
#pragma unroll
            for (int i = 0; i < 8; i++)
#pragma unroll
                for (int j = 0; j < 8; j++) acc[i][j] += af[i] * bf[j];
        }
        __syncthreads();
    }
    float kbr[8];
#pragma unroll
    for (int j = 0; j < 8; j++) kbr[j] = kb[bn * BN + nfrag + j];
    size_t nbase = (size_t)bn * BN + nfrag;
#pragma unroll
    for (int i = 0; i < 8; i++) {
        size_t m = (size_t)bm * BM + mfrag + i;
        float4 v0 = {acc[i][0] + kbr[0], acc[i][1] + kbr[1], acc[i][2] + kbr[2], acc[i][3] + kbr[3]};
        float4 v1 = {acc[i][4] + kbr[4], acc[i][5] + kbr[5], acc[i][6] + kbr[6], acc[i][7] + kbr[7]};
        *(float4*)(d_kern + m * NLAY + nbase) = v0;
        *(float4*)(d_kern + m * NLAY + nbase + 4) = v1;
    }
}

// ---------------- bias head: kbias[m][n] = A[m] . bias_w[n] + bias_b[n] ----------------
__global__ void kbias_k(const float* __restrict__ bw, const float* __restrict__ bb) {
    __shared__ float As8[8][KD];
    int m0 = blockIdx.x * 8;
    for (int v = threadIdx.x; v < 8 * KD; v += 256)
        As8[v / KD][v % KD] = d_A[(size_t)m0 * KD + v];
    __syncthreads();
    int n = threadIdx.x;  // 256
    const float* wr = bw + n * KD;
    float b0 = bb[n];
    float acc[8];
#pragma unroll
    for (int r = 0; r < 8; r++) acc[r] = b0;
    for (int f = 0; f < KD; f++) {
        float wv = wr[f];
#pragma unroll
        for (int r = 0; r < 8; r++) acc[r] += As8[r][f] * wv;
    }
#pragma unroll
    for (int r = 0; r < 8; r++) d_kbias[(size_t)(m0 + r) * 256 + n] = acc[r];
}

// ---------------- convt_pre: lrelu + ConvTranspose1d(k=16, stride=8, pad=4) ----------------
__global__ void convt_k(const float* __restrict__ x, const float* __restrict__ w,
                        const float* __restrict__ b) {
    int idx = blockIdx.x * blockDim.x + threadIdx.x;
    if (idx >= Bq * CIN * TT) return;
    int t = idx & (TT - 1);
    int co = (idx / TT) & (CIN - 1);
    int bb = idx / (TT * CIN);
    float acc = b[co];
    int j0 = (t + 4) & 7;
#pragma unroll
    for (int jj = 0; jj < 2; jj++) {
        int j = j0 + jj * 8;
        int s = (t + 4 - j) >> 3;          // arithmetic shift: negative -> rejected
        if (s >= 0 && s < LC) {
            const float* xr = x + (size_t)bb * CIN * LC + s;
            for (int ci = 0; ci < CIN; ci++)
                acc += lrelu(xr[ci * LC]) * w[(ci * CIN + co) * 16 + j];
        }
    }
    d_xx0[idx] = acc;
}

// ---------------- fused LVC layer: dilated conv + window + einsum + gated residual ----------------
// one block per (b, l): loads kern slice (24KB) + xx window, everything else in smem.
__global__ void __launch_bounds__(256) lvc_k(const float* __restrict__ cbw,
                                             const float* __restrict__ cbb,
                                             int insel, int outsel, float* __restrict__ outext,
                                             int layer, int dil) {
    __shared__ float xs[CIN][66];      // lrelu(xx) window, zero-padded
    __shared__ float ywin[CIN][12];    // lrelu(conv) at t = l*8-1 .. l*8+8 (10 used)
    __shared__ float ko[CIN * COUT * 3];
    __shared__ float osm[512];
    int l = blockIdx.x, bb = blockIdx.y, tid = threadIdx.x;
    const float* xxin = insel ? d_xx1 : d_xx0;
    float* xxout = (outsel == 2) ? outext : (outsel ? d_xx1 : d_xx0);
    size_t m = (size_t)bb * LC + l;

    const float* kp = d_kern + m * NLAY;
    for (int v = tid; v < CIN * COUT * 3; v += 256) ko[v] = kp[v];

    const float* xb = xxin + (size_t)bb * CIN * TT;
    int t0 = l * HOP - 1 - dil;
    int wlen = 10 + 2 * dil;           // <= 64 (dil=27)
    for (int v = tid; v < CIN * wlen; v += 256) {
        int ci = v / wlen, p = v - ci * wlen;
        int t = t0 + p;
        float xv = (t >= 0 && t < TT) ? xb[(size_t)ci * TT + t] : 0.f;
        xs[ci][p] = lrelu(xv);
    }
    __syncthreads();

    // conv at 10 positions x 32 channels; tap index in xs = pos + k*dil
    for (int v = tid; v < CIN * 10; v += 256) {
        int pos = v % 10, co = v / 10;
        int t = l * HOP - 1 + pos;
        float acc = cbb[co];
        const float* wr = cbw + co * CIN * 3;
        for (int ci = 0; ci < CIN; ci++) {
            acc += xs[ci][pos] * wr[ci * 3]
                 + xs[ci][pos + dil] * wr[ci * 3 + 1]
                 + xs[ci][pos + 2 * dil] * wr[ci * 3 + 2];
        }
        ywin[co][pos] = (t >= 0 && t < TT) ? lrelu(acc) : 0.f;  // window zero-pad
    }
    __syncthreads();

    // o[co2][h] = sum_{ci,k} ywin[ci][h+k] * ko[ci][co2][k] + kbias
    for (int u = tid; u < 512; u += 256) {
        int co2 = u >> 3, h = u & 7;
        float acc = d_kbias[m * 256 + layer * 64 + co2];
        for (int ci = 0; ci < CIN; ci++) {
            const float* kc = ko + (ci * COUT + co2) * 3;
            acc += ywin[ci][h] * kc[0] + ywin[ci][h + 1] * kc[1] + ywin[ci][h + 2] * kc[2];
        }
        osm[u] = acc;
    }
    __syncthreads();

    // gated residual: xx += sigmoid(o[:32]) * tanh(o[32:])
    {
        int co = tid >> 3, h = tid & 7;
        float o1 = osm[tid];
        float o2 = osm[tid + 256];
        float g = (1.f / (1.f + expf(-o1))) * tanhf(o2);
        int t = l * HOP + h;
        size_t oi = ((size_t)bb * CIN + co) * TT + t;
        xxout[oi] = xxin[oi] + g;
    }
}

// ---------------- launch ----------------
extern "C" void kernel_launch(void* const* d_in, const int* in_sizes, int n_in,
                              void* d_out, int out_size) {
    const float* x      = (const float*)d_in[0];
    const float* c      = (const float*)d_in[1];
    const float* in_w   = (const float*)d_in[2];
    const float* in_b   = (const float*)d_in[3];
    const float* res_ws = (const float*)d_in[4];
    const float* res_bs = (const float*)d_in[5];
    const float* ker_w  = (const float*)d_in[6];
    const float* ker_b  = (const float*)d_in[7];
    const float* bias_w = (const float*)d_in[8];
    const float* bias_b = (const float*)d_in[9];
    const float* ct_w   = (const float*)d_in[10];
    const float* ct_b   = (const float*)d_in[11];
    const float* cb_ws  = (const float*)d_in[12];
    const float* cb_bs  = (const float*)d_in[13];
    float* out = (float*)d_out;

    conv_in_k<<<dim3(HID, Bq), LC>>>(c, in_w, in_b);
    for (int j = 0; j < 3; j++) {
        conv_res_k<<<dim3(HID, Bq), LC>>>(res_ws + (size_t)(j * 2) * HID * HID * 3,
                                          res_bs + (j * 2) * HID, 0, 1, 0);
        conv_res_k<<<dim3(HID, Bq), LC>>>(res_ws + (size_t)(j * 2 + 1) * HID * HID * 3,
                                          res_bs + (j * 2 + 1) * HID, 1, 0, 1);
    }
    build_A_k<<<Bq * LC, KD>>>();
    kbias_k<<<(Bq * LC) / 8, 256>>>(bias_w, bias_b);
    convt_k<<<(Bq * CIN * TT + 255) / 256, 256>>>(x, ct_w, ct_b);

    const int dils[4] = {1, 3, 9, 27};
    for (int i = 0; i < 4; i++) {
        // per-layer kernel-prediction GEMM: ker_w rows are layer-major contiguous
        gemm_k<<<dim3(NLAY / BN, (Bq * LC) / BM), 256>>>(ker_w + (size_t)i * NLAY * KD,
                                                         ker_b + (size_t)i * NLAY);
        int insel = i & 1;
        int outsel = (i == 3) ? 2 : ((i + 1) & 1);
        lvc_k<<<dim3(LC, Bq), 256>>>(cb_ws + (size_t)i * CIN * CIN * 3, cb_bs + i * CIN,
                                     insel, outsel, out, i, dils[i]);
    }
}

// round 4
// speedup vs baseline: 1.4245x; 1.4245x over previous
#include <cuda_runtime.h>
#include <cuda_bf16.h>
#include <math.h>
#include <stdint.h>

#define Bq 16
#define CIN 32
#define CCOND 100
#define LC 512
#define HOP 8
#define HID 64
#define NL 4
#define COUT 64
#define TT 4096
#define KD 192          // 64*3 features for the k=3 conv-as-GEMM
#define NLAY 6144       // CIN*COUT*3 = per-layer kernel channels
#define SLOPE 0.2f

// ---------------- scratch (static __device__, no allocations) ----------------
__device__ float d_h[Bq * HID * LC];
__device__ float d_tmp[Bq * HID * LC];
__device__ float d_A[Bq * LC * KD];                    // im2col of h (fp32, for kbias)
__device__ __align__(16) __nv_bfloat16 d_Ah[Bq * LC * KD];
__device__ __align__(16) __nv_bfloat16 d_Al[Bq * LC * KD];
__device__ __align__(16) __nv_bfloat16 d_Wh[NLAY * KD];
__device__ __align__(16) __nv_bfloat16 d_Wl[NLAY * KD];
__device__ float d_kern[(size_t)Bq * LC * NLAY];       // per-layer slice [m][ci][o][k] (~201MB)
__device__ float d_kbias[Bq * LC * NL * COUT];         // [m][layer][o]
__device__ float d_xx0[Bq * CIN * TT];
__device__ float d_xx1[Bq * CIN * TT];

__device__ __forceinline__ float lrelu(float v) { return v >= 0.f ? v : SLOPE * v; }

// ---------------- kernel predictor: input conv (k=5, pad=2) + lrelu, 4 outputs/thread ----------------
__global__ void conv_in_k(const float* __restrict__ c, const float* __restrict__ w,
                          const float* __restrict__ b) {
    int co = blockIdx.x, bb = blockIdx.y;
    int l0 = threadIdx.x * 4;                     // 128 threads
    const float* cb = c + (size_t)bb * CCOND * LC;
    const float* wr = w + co * CCOND * 5;
    float a0, a1, a2, a3;
    a0 = a1 = a2 = a3 = b[co];
    for (int ci = 0; ci < CCOND; ci++) {
        const float* cr = cb + ci * LC;
        float4 xm = *(const float4*)(cr + l0);
        float xm2 = (l0 >= 2) ? cr[l0 - 2] : 0.f;
        float xm1 = (l0 >= 1) ? cr[l0 - 1] : 0.f;
        float xp4 = (l0 + 4 < LC) ? cr[l0 + 4] : 0.f;
        float xp5 = (l0 + 5 < LC) ? cr[l0 + 5] : 0.f;
        float w0 = wr[ci * 5], w1 = wr[ci * 5 + 1], w2 = wr[ci * 5 + 2],
              w3 = wr[ci * 5 + 3], w4 = wr[ci * 5 + 4];
        a0 += xm2 * w0 + xm1 * w1 + xm.x * w2 + xm.y * w3 + xm.z * w4;
        a1 += xm1 * w0 + xm.x * w1 + xm.y * w2 + xm.z * w3 + xm.w * w4;
        a2 += xm.x * w0 + xm.y * w1 + xm.z * w2 + xm.w * w3 + xp4 * w4;
        a3 += xm.y * w0 + xm.z * w1 + xm.w * w2 + xp4 * w3 + xp5 * w4;
    }
    float4 o = {lrelu(a0), lrelu(a1), lrelu(a2), lrelu(a3)};
    *(float4*)(d_h + ((size_t)bb * HID + co) * LC + l0) = o;
}

// ---------------- residual-block conv (k=3, pad=1), lrelu, optional add, 4 outputs/thread ----------------
__global__ void conv_res_k(const float* __restrict__ w, const float* __restrict__ b,
                           int srcTmp, int dstTmp, int doAdd) {
    int co = blockIdx.x, bb = blockIdx.y;
    int l0 = threadIdx.x * 4;                     // 128 threads
    const float* in = srcTmp ? d_tmp : d_h;
    float* out = dstTmp ? d_tmp : d_h;
    const float* ib = in + (size_t)bb * HID * LC;
    const float* wr = w + co * HID * 3;
    float a0, a1, a2, a3;
    a0 = a1 = a2 = a3 = b[co];
    for (int ci = 0; ci < HID; ci++) {
        const float* xr = ib + ci * LC;
        float4 xm = *(const float4*)(xr + l0);
        float xl = (l0 >= 1) ? xr[l0 - 1] : 0.f;
        float xrg = (l0 + 4 < LC) ? xr[l0 + 4] : 0.f;
        float w0 = wr[ci * 3], w1 = wr[ci * 3 + 1], w2 = wr[ci * 3 + 2];
        a0 += xl * w0 + xm.x * w1 + xm.y * w2;
        a1 += xm.x * w0 + xm.y * w1 + xm.z * w2;
        a2 += xm.y * w0 + xm.z * w1 + xm.w * w2;
        a3 += xm.z * w0 + xm.w * w1 + xrg * w2;
    }
    float4 o = {lrelu(a0), lrelu(a1), lrelu(a2), lrelu(a3)};
    if (doAdd) {
        float4 h0 = *(const float4*)(d_h + ((size_t)bb * HID + co) * LC + l0);
        o.x += h0.x; o.y += h0.y; o.z += h0.z; o.w += h0.w;
    }
    *(float4*)(out + ((size_t)bb * HID + co) * LC + l0) = o;
}

// ---------------- im2col + bf16 hi/lo split: A[m][c2*3+kk] = h[b][c2][l+kk-1] ----------------
__global__ void convA_k() {
    int m = blockIdx.x;
    int bb = m / LC, l = m % LC;
    int f = threadIdx.x;            // 192
    int c2 = f / 3, kk = f % 3;
    int t = l + kk - 1;
    float v = (t >= 0 && t < LC) ? d_h[((size_t)bb * HID + c2) * LC + t] : 0.f;
    d_A[(size_t)m * KD + f] = v;
    __nv_bfloat16 h = __float2bfloat16(v);
    d_Ah[(size_t)m * KD + f] = h;
    d_Al[(size_t)m * KD + f] = __float2bfloat16(v - __bfloat162float(h));
}

// ---------------- per-layer W hi/lo split ----------------
__global__ void convW_k(const float* __restrict__ W) {
    int i = blockIdx.x * 256 + threadIdx.x;
    if (i >= NLAY * KD) return;
    float v = W[i];
    __nv_bfloat16 h = __float2bfloat16(v);
    d_Wh[i] = h;
    d_Wl[i] = __float2bfloat16(v - __bfloat162float(h));
}

// ---------------- tensor-core GEMM via mma.sync (per layer) ----------------
// C[m][n] = sum_f A[m][f]*W[n][f] + kb[n].  M=8192, N=6144, K=192.
// 128x128 tile, 8 warps (2x4), warp = 64x32, bf16 hi/lo split: hh + hl + lh.
#define CH 64
#define PAD 8
#define STR (CH + PAD)   // 72 elements, 144B row stride (conflict-free for quads)
#define GMMA_SMEM (4 * 128 * STR * 2 + 512)

__device__ __forceinline__ void mma16816(float* d, const uint32_t* a, const uint32_t* b) {
    asm volatile(
        "mma.sync.aligned.m16n8k16.row.col.f32.bf16.bf16.f32 "
        "{%0,%1,%2,%3}, {%4,%5,%6,%7}, {%8,%9}, {%0,%1,%2,%3};"
        : "+f"(d[0]), "+f"(d[1]), "+f"(d[2]), "+f"(d[3])
        : "r"(a[0]), "r"(a[1]), "r"(a[2]), "r"(a[3]), "r"(b[0]), "r"(b[1]));
}

__global__ void __launch_bounds__(256, 2) gemm_mma(const float* __restrict__ kb) {
    extern __shared__ char smem[];
    __nv_bfloat16* sAh = (__nv_bfloat16*)smem;
    __nv_bfloat16* sAl = sAh + 128 * STR;
    __nv_bfloat16* sWh = sAl + 128 * STR;
    __nv_bfloat16* sWl = sWh + 128 * STR;
    float* kbs = (float*)(sWl + 128 * STR);
    int tid = threadIdx.x, wid = tid >> 5, lane = tid & 31;
    int bm = blockIdx.y, bn = blockIdx.x;
    int wm = (wid >> 2) * 64, wn = (wid & 3) * 32;
    int gid = lane >> 2, tg = lane & 3;

    float acc[4][4][4];
#pragma unroll
    for (int i = 0; i < 4; i++)
#pragma unroll
        for (int j = 0; j < 4; j++)
#pragma unroll
            for (int q = 0; q < 4; q++) acc[i][j][q] = 0.f;

    if (tid < 128) kbs[tid] = kb[bn * 128 + tid];

    for (int c = 0; c < 3; c++) {
        const __nv_bfloat16* gAh = d_Ah + (size_t)(bm * 128) * KD + c * CH;
        const __nv_bfloat16* gAl = d_Al + (size_t)(bm * 128) * KD + c * CH;
        const __nv_bfloat16* gWh = d_Wh + (size_t)(bn * 128) * KD + c * CH;
        const __nv_bfloat16* gWl = d_Wl + (size_t)(bn * 128) * KD + c * CH;
        __syncthreads();
#pragma unroll
        for (int i = 0; i < 4; i++) {
            int v = tid + i * 256;          // 0..1023: 128 rows x 8 x 16B
            int row = v >> 3, seg = v & 7;
            int so = row * STR + seg * 8;
            size_t go = (size_t)row * KD + seg * 8;
            *(uint4*)(sAh + so) = *(const uint4*)(gAh + go);
            *(uint4*)(sAl + so) = *(const uint4*)(gAl + go);
            *(uint4*)(sWh + so) = *(const uint4*)(gWh + go);
            *(uint4*)(sWl + so) = *(const uint4*)(gWl + go);
        }
        __syncthreads();
#pragma unroll
        for (int p = 0; p < 3; p++) {       // hh, hl, lh
            const __nv_bfloat16* pa = (p == 2) ? sAl : sAh;
            const __nv_bfloat16* pb = (p == 1) ? sWl : sWh;
#pragma unroll
            for (int ks = 0; ks < 4; ks++) {
                uint32_t af[4][4], bfr[4][2];
#pragma unroll
                for (int tm = 0; tm < 4; tm++) {
                    const __nv_bfloat16* b0 = pa + (wm + tm * 16 + gid) * STR + ks * 16 + tg * 2;
                    af[tm][0] = *(const uint32_t*)b0;
                    af[tm][1] = *(const uint32_t*)(b0 + 8 * STR);
                    af[tm][2] = *(const uint32_t*)(b0 + 8);
                    af[tm][3] = *(const uint32_t*)(b0 + 8 * STR + 8);
                }
#pragma unroll
                for (int tn = 0; tn < 4; tn++) {
                    const __nv_bfloat16* c0 = pb + (wn + tn * 8 + gid) * STR + ks * 16 + tg * 2;
                    bfr[tn][0] = *(const uint32_t*)c0;
                    bfr[tn][1] = *(const uint32_t*)(c0 + 8);
                }
#pragma unroll
                for (int tm = 0; tm < 4; tm++)
#pragma unroll
                    for (int tn = 0; tn < 4; tn++)
                        mma16816(acc[tm][tn], af[tm], bfr[tn]);
            }
        }
    }

    // epilogue: add bias, write d_kern
#pragma unroll
    for (int tm = 0; tm < 4; tm++) {
        size_t m0 = (size_t)(bm * 128 + wm + tm * 16 + gid);
        float* r0 = d_kern + m0 * NLAY + bn * 128;
        float* r1 = r0 + (size_t)8 * NLAY;
#pragma unroll
        for (int tn = 0; tn < 4; tn++) {
            int nl = wn + tn * 8 + tg * 2;
            float kb0 = kbs[nl], kb1 = kbs[nl + 1];
            float2 v0 = {acc[tm][tn][0] + kb0, acc[tm][tn][1] + kb1};
            float2 v1 = {acc[tm][tn][2] + kb0, acc[tm][tn][3] + kb1};
            *(float2*)(r0 + nl) = v0;
            *(float2*)(r1 + nl) = v1;
        }
    }
}

// ---------------- bias head: kbias[m][n] = A[m] . bias_w[n] + bias_b[n] ----------------
__global__ void kbias_k(const float* __restrict__ bw, const float* __restrict__ bb) {
    __shared__ float As8[8][KD];
    int m0 = blockIdx.x * 8;
    for (int v = threadIdx.x; v < 8 * KD; v += 256)
        As8[v / KD][v % KD] = d_A[(size_t)m0 * KD + v];
    __syncthreads();
    int n = threadIdx.x;  // 256
    const float* wr = bw + n * KD;
    float b0 = bb[n];
    float acc[8];
#pragma unroll
    for (int r = 0; r < 8; r++) acc[r] = b0;
    for (int f = 0; f < KD; f++) {
        float wv = wr[f];
#pragma unroll
        for (int r = 0; r < 8; r++) acc[r] += As8[r][f] * wv;
    }
#pragma unroll
    for (int r = 0; r < 8; r++) d_kbias[(size_t)(m0 + r) * 256 + n] = acc[r];
}

// ---------------- convt_pre: lrelu + ConvTranspose1d(k=16, stride=8, pad=4) ----------------
__global__ void convt_k(const float* __restrict__ x, const float* __restrict__ w,
                        const float* __restrict__ b) {
    int idx = blockIdx.x * blockDim.x + threadIdx.x;
    if (idx >= Bq * CIN * TT) return;
    int t = idx & (TT - 1);
    int co = (idx / TT) & (CIN - 1);
    int bb = idx / (TT * CIN);
    float acc = b[co];
    int j0 = (t + 4) & 7;
#pragma unroll
    for (int jj = 0; jj < 2; jj++) {
        int j = j0 + jj * 8;
        int s = (t + 4 - j) >> 3;          // arithmetic shift: negative -> rejected
        if (s >= 0 && s < LC) {
            const float* xr = x + (size_t)bb * CIN * LC + s;
            for (int ci = 0; ci < CIN; ci++)
                acc += lrelu(xr[ci * LC]) * w[(ci * CIN + co) * 16 + j];
        }
    }
    d_xx0[idx] = acc;
}

// ---------------- fused LVC layer: dilated conv + window + einsum + gated residual ----------------
__global__ void __launch_bounds__(256) lvc_k(const float* __restrict__ cbw,
                                             const float* __restrict__ cbb,
                                             int insel, int outsel, float* __restrict__ outext,
                                             int layer, int dil) {
    __shared__ float xs[CIN][66];      // lrelu(xx) window, zero-padded
    __shared__ float ywin[CIN][12];    // lrelu(conv) at t = l*8-1 .. l*8+8 (10 used)
    __shared__ float ko[CIN * COUT * 3];
    __shared__ float osm[512];
    int l = blockIdx.x, bb = blockIdx.y, tid = threadIdx.x;
    const float* xxin = insel ? d_xx1 : d_xx0;
    float* xxout = (outsel == 2) ? outext : (outsel ? d_xx1 : d_xx0);
    size_t m = (size_t)bb * LC + l;

    const float* kp = d_kern + m * NLAY;
    for (int v = tid; v < CIN * COUT * 3; v += 256) ko[v] = kp[v];

    const float* xb = xxin + (size_t)bb * CIN * TT;
    int t0 = l * HOP - 1 - dil;
    int wlen = 10 + 2 * dil;           // <= 64 (dil=27)
    for (int v = tid; v < CIN * wlen; v += 256) {
        int ci = v / wlen, p = v - ci * wlen;
        int t = t0 + p;
        float xv = (t >= 0 && t < TT) ? xb[(size_t)ci * TT + t] : 0.f;
        xs[ci][p] = lrelu(xv);
    }
    __syncthreads();

    // conv at 10 positions x 32 channels; tap index in xs = pos + k*dil
    for (int v = tid; v < CIN * 10; v += 256) {
        int pos = v % 10, co = v / 10;
        int t = l * HOP - 1 + pos;
        float acc = cbb[co];
        const float* wr = cbw + co * CIN * 3;
        for (int ci = 0; ci < CIN; ci++) {
            acc += xs[ci][pos] * wr[ci * 3]
                 + xs[ci][pos + dil] * wr[ci * 3 + 1]
                 + xs[ci][pos + 2 * dil] * wr[ci * 3 + 2];
        }
        ywin[co][pos] = (t >= 0 && t < TT) ? lrelu(acc) : 0.f;  // window zero-pad
    }
    __syncthreads();

    // o[co2][h] = sum_{ci,k} ywin[ci][h+k] * ko[ci][co2][k] + kbias
    for (int u = tid; u < 512; u += 256) {
        int co2 = u >> 3, h = u & 7;
        float acc = d_kbias[m * 256 + layer * 64 + co2];
        for (int ci = 0; ci < CIN; ci++) {
            const float* kc = ko + (ci * COUT + co2) * 3;
            acc += ywin[ci][h] * kc[0] + ywin[ci][h + 1] * kc[1] + ywin[ci][h + 2] * kc[2];
        }
        osm[u] = acc;
    }
    __syncthreads();

    // gated residual: xx += sigmoid(o[:32]) * tanh(o[32:])
    {
        int co = tid >> 3, h = tid & 7;
        float o1 = osm[tid];
        float o2 = osm[tid + 256];
        float g = (1.f / (1.f + expf(-o1))) * tanhf(o2);
        int t = l * HOP + h;
        size_t oi = ((size_t)bb * CIN + co) * TT + t;
        xxout[oi] = xxin[oi] + g;
    }
}

// ---------------- launch ----------------
extern "C" void kernel_launch(void* const* d_in, const int* in_sizes, int n_in,
                              void* d_out, int out_size) {
    const float* x      = (const float*)d_in[0];
    const float* c      = (const float*)d_in[1];
    const float* in_w   = (const float*)d_in[2];
    const float* in_b   = (const float*)d_in[3];
    const float* res_ws = (const float*)d_in[4];
    const float* res_bs = (const float*)d_in[5];
    const float* ker_w  = (const float*)d_in[6];
    const float* ker_b  = (const float*)d_in[7];
    const float* bias_w = (const float*)d_in[8];
    const float* bias_b = (const float*)d_in[9];
    const float* ct_w   = (const float*)d_in[10];
    const float* ct_b   = (const float*)d_in[11];
    const float* cb_ws  = (const float*)d_in[12];
    const float* cb_bs  = (const float*)d_in[13];
    float* out = (float*)d_out;

    cudaFuncSetAttribute(gemm_mma, cudaFuncAttributeMaxDynamicSharedMemorySize, GMMA_SMEM);

    conv_in_k<<<dim3(HID, Bq), 128>>>(c, in_w, in_b);
    for (int j = 0; j < 3; j++) {
        conv_res_k<<<dim3(HID, Bq), 128>>>(res_ws + (size_t)(j * 2) * HID * HID * 3,
                                           res_bs + (j * 2) * HID, 0, 1, 0);
        conv_res_k<<<dim3(HID, Bq), 128>>>(res_ws + (size_t)(j * 2 + 1) * HID * HID * 3,
                                           res_bs + (j * 2 + 1) * HID, 1, 0, 1);
    }
    convA_k<<<Bq * LC, KD>>>();
    kbias_k<<<(Bq * LC) / 8, 256>>>(bias_w, bias_b);
    convt_k<<<(Bq * CIN * TT + 255) / 256, 256>>>(x, ct_w, ct_b);

    const int dils[4] = {1, 3, 9, 27};
    for (int i = 0; i < 4; i++) {
        convW_k<<<(NLAY * KD + 255) / 256, 256>>>(ker_w + (size_t)i * NLAY * KD);
        gemm_mma<<<dim3(NLAY / 128, (Bq * LC) / 128), 256, GMMA_SMEM>>>(ker_b + (size_t)i * NLAY);
        int insel = i & 1;
        int outsel = (i == 3) ? 2 : ((i + 1) & 1);
        lvc_k<<<dim3(LC, Bq), 256>>>(cb_ws + (size_t)i * CIN * CIN * 3, cb_bs + i * CIN,
                                     insel, outsel, out, i, dils[i]);
    }
}